// round 12
// baseline (speedup 1.0000x reference)
#include <cuda_runtime.h>
#include <cuda_fp16.h>
#include <cstdint>

#define HW   196
#define NC   128
#define NB   8
#define CIN  512
#define NPIX 256
#define MM   16384
#define EPSV 1e-11f
#define KPAD 208            // K padded to 13 k-steps of 16
#define XDW  424            // global doubled-row width (halfs)
#define XRS  232            // Xr smem row stride (halfs)
#define XDS  224            // Xd smem row width (halfs)
#define WSZ  802816         // 4096*196 = 49*16384

// ---------------- device scratch (.bss zero-init) --------------------------
__device__ float  g_yp  [4][NB * NC * NPIX];
__device__ __half g_xrh [NB * NC * KPAD];
__device__ __half g_xdh [NB * NC * XDW];
__device__ __half g_xdh1[NB * NC * XDW];
__device__ float  g_W   [(size_t)NB * WSZ];   // folded max, fits L2 (25.7MB)
__device__ float  g_Q   [NB * 7 * 16384];
__device__ float  g_part[NB * 64];
__device__ float  g_norm[NB];

// ---------------- Kernel A: partial y = W @ x (K-split by 4) ---------------
__global__ void __launch_bounds__(256) pw4(const float* __restrict__ x,
                                           const float* __restrict__ w) {
    __shared__ float xs[32][64];
    __shared__ float ws[32][32];
    int bz = blockIdx.z, b = bz >> 2, ks = bz & 3;
    int o0 = blockIdx.y * 32, px0 = blockIdx.x * 64;
    int tid = threadIdx.x, px = tid & 63, og = tid >> 6;
    float acc[8];
#pragma unroll
    for (int u = 0; u < 8; u++) acc[u] = 0.f;
    const float* xb = x + b * CIN * NPIX;
    int ibase = ks * 128;
    for (int i0 = ibase; i0 < ibase + 128; i0 += 32) {
        __syncthreads();
#pragma unroll
        for (int r = 0; r < 8; r++) {
            int idx = tid + r * 256;
            xs[idx >> 6][idx & 63] = xb[(i0 + (idx >> 6)) * NPIX + px0 + (idx & 63)];
        }
#pragma unroll
        for (int r = 0; r < 4; r++) {
            int idx = tid + r * 256;
            ws[idx >> 5][idx & 31] = w[(o0 + (idx >> 5)) * CIN + i0 + (idx & 31)];
        }
        __syncthreads();
#pragma unroll
        for (int i = 0; i < 32; i++) {
            float xv = xs[i][px];
#pragma unroll
            for (int u = 0; u < 8; u++)
                acc[u] = fmaf(ws[og * 8 + u][i], xv, acc[u]);
        }
    }
    float* yb = g_yp[ks] + b * NC * NPIX;
#pragma unroll
    for (int u = 0; u < 8; u++)
        yb[(o0 + og * 8 + u) * NPIX + px0 + px] = acc[u];
}

// ---------------- Kernel B: sum + relu + gaussian + fp16 prep ---------------
__global__ void __launch_bounds__(256) prep() {
    __shared__ float s[256];
    int b = blockIdx.y, c = blockIdx.x, t = threadIdx.x;
    int off = (b * NC + c) * NPIX + t;
    s[t] = fmaxf(g_yp[0][off] + g_yp[1][off] + g_yp[2][off] + g_yp[3][off], 0.f);
    __syncthreads();
    if (t < HW) {
        const float G0 = 0.63661977f, G1 = 0.08615711f, G2 = 0.01166010f;
        int oy = t / 14, ox = t - oy * 14;
        int r0 = oy * 16 + ox, r1 = r0 + 16, r2 = r0 + 32;
        float v = G2 * (s[r0] + s[r0 + 2] + s[r2] + s[r2 + 2])
                + G1 * (s[r0 + 1] + s[r1] + s[r1 + 2] + s[r2 + 1])
                + G0 * s[r1 + 1];
        __half h = __float2half_rn(v);
        g_xrh[(b * NC + c) * KPAD + (195 - t)] = h;
        __half* xd = g_xdh + (size_t)(b * NC + c) * XDW;
        xd[t]      = h;
        xd[t + HW] = h;
        if (t < 32) xd[t + 392] = h;
        __half* x1 = g_xdh1 + (size_t)(b * NC + c) * XDW;
        x1[t + 195] = h;
        if (t) x1[t - 1] = h;
        if (t < 33) x1[t + 391] = h;
    }
}

// ---------------- shim: zero g_W + g_part; keeps corr in ncu slot 4 --------
__global__ void __launch_bounds__(256) zeroWk() {
    size_t i = (size_t)blockIdx.x * 256 + threadIdx.x;   // 6272*256 float4
    ((float4*)g_W)[i] = make_float4(0.f, 0.f, 0.f, 0.f);
    if (i < NB * 64) g_part[i] = 0.f;
}

__device__ __forceinline__ uint32_t smem_u32(const void* p) {
    uint32_t a;
    asm("{ .reg .u64 t; cvta.to.shared.u64 t, %1; cvt.u32.u64 %0, t; }"
        : "=r"(a) : "l"(p));
    return a;
}

// ---------------- Kernel C: symmetric fp16 mma corr + atomic fold ----------
// R[a,c,p]=R[c,a,p]: only 32x32 (a,c) block pairs i<=j (10 of 16).
// CTA: 32 a x (32 c x 8 p). 8 warps, warp tile 32m x 32n (4 c x 8 p each).
// Epilogue RED-maxes into W[(a&31)*128+c] and mirror W[(c&31)*128+a].
__global__ void __launch_bounds__(256, 3) corr10() {
    extern __shared__ char dyn[];
    __half* XrS = (__half*)dyn;                  // [32][XRS]  14848 B
    __half* XdA = (__half*)(dyn + 14848);        // [32][XDS]
    __half* XdB = XdA + 32 * XDS + 16;           // [32][XDS], bank shift

    int b  = blockIdx.z;
    int P  = blockIdx.y;
    int p0 = blockIdx.x * 8;
    int tid = threadIdx.x;
    // pair tables packed 2 bits each: pi = 0000111223, pj = 0123123233
    int i4 = (0xE9500u >> (2 * P)) & 3;
    int j4 = (0xFB9E4u >> (2 * P)) & 3;
    int a0 = i4 * 32, c0 = j4 * 32;

    // stage XrS: rows a0..a0+31, 26 int4 each
    {
        const int4* xr = (const int4*)(g_xrh + (size_t)b * NC * KPAD);
        for (int i = tid; i < 832; i += 256) {
            int r = i / 26, q = i - r * 26;
            *(int4*)(XrS + r * XRS + q * 8) = xr[(a0 + r) * 26 + q];
        }
    }
    // stage XdA/XdB: rows c0..c0+31, 28 int4 each, both parities
    for (int i = tid; i < 1792; i += 256) {
        int sel = (i >= 896);
        int ii = sel ? (i - 896) : i;
        int r = ii / 28, q = ii - r * 28;
        const __half* src = (sel ? g_xdh1 : g_xdh)
                          + (size_t)(b * NC + c0 + r) * XDW + p0 + q * 8;
        __half* dst = (sel ? XdB : XdA) + r * XDS + q * 8;
        *(int4*)dst = *(const int4*)src;
    }
    __syncthreads();

    int lane = tid & 31, wn = tid >> 5;
    int lr = lane >> 2, lk = lane & 3;

    uint32_t a_addr[2];
    {
        int arow = (lane & 7) + ((lane >> 3) & 1) * 8;
        int acol = (lane >> 4) * 8;
        uint32_t base = smem_u32(XrS);
#pragma unroll
        for (int mi = 0; mi < 2; mi++)
            a_addr[mi] = base + (uint32_t)(((arow + mi * 16) * XRS + acol) * 2);
    }

    const __half* brow[4];
    {
        const __half* pb = (lr & 1) ? (XdA + lr + 1) : (XdB + lr);
#pragma unroll
        for (int nt = 0; nt < 4; nt++)
            brow[nt] = pb + (wn * 4 + nt) * XDS + lk * 2;
    }

    float acc[2][4][4];
#pragma unroll
    for (int mi = 0; mi < 2; mi++)
#pragma unroll
        for (int nt = 0; nt < 4; nt++)
#pragma unroll
            for (int u = 0; u < 4; u++) acc[mi][nt][u] = 0.f;

#pragma unroll
    for (int k = 0; k < KPAD; k += 16) {
        uint32_t af[2][4];
#pragma unroll
        for (int mi = 0; mi < 2; mi++) {
            asm volatile(
                "ldmatrix.sync.aligned.m8n8.x4.shared.b16 {%0,%1,%2,%3}, [%4];"
                : "=r"(af[mi][0]), "=r"(af[mi][1]),
                  "=r"(af[mi][2]), "=r"(af[mi][3])
                : "r"(a_addr[mi] + (uint32_t)(k * 2)));
        }
#pragma unroll
        for (int nt = 0; nt < 4; nt++) {
            uint32_t b0 = *(const uint32_t*)(brow[nt] + k);
            uint32_t b1 = *(const uint32_t*)(brow[nt] + k + 8);
#pragma unroll
            for (int mi = 0; mi < 2; mi++) {
                asm volatile(
                    "mma.sync.aligned.m16n8k16.row.col.f32.f16.f16.f32 "
                    "{%0,%1,%2,%3},{%4,%5,%6,%7},{%8,%9},{%0,%1,%2,%3};"
                    : "+f"(acc[mi][nt][0]), "+f"(acc[mi][nt][1]),
                      "+f"(acc[mi][nt][2]), "+f"(acc[mi][nt][3])
                    : "r"(af[mi][0]), "r"(af[mi][1]),
                      "r"(af[mi][2]), "r"(af[mi][3]),
                      "r"(b0), "r"(b1));
            }
        }
    }

    // epilogue: idempotent atomic max fold (values >= 0 -> int-bit order OK)
    int pe = p0 + lk * 2;
    if (pe < HW) {
        int* Wb = (int*)(g_W + (size_t)b * WSZ);
#pragma unroll
        for (int mi = 0; mi < 2; mi++) {
#pragma unroll
            for (int nt = 0; nt < 4; nt++) {
                int c = c0 + wn * 4 + nt;
#pragma unroll
                for (int h = 0; h < 2; h++) {
                    int a = a0 + mi * 16 + lr + h * 8;
                    int v0 = __float_as_int(acc[mi][nt][2 * h + 0]);
                    int v1 = __float_as_int(acc[mi][nt][2 * h + 1]);
                    int f0 = ((a & 31) * NC + c) * HW + pe;   // primary
                    int f1 = ((c & 31) * NC + a) * HW + pe;   // mirror
                    atomicMax(Wb + f0,     v0);
                    atomicMax(Wb + f0 + 1, v1);
                    atomicMax(Wb + f1,     v0);
                    atomicMax(Wb + f1 + 1, v1);
                }
            }
        }
    }
}

// ---------------- Kernel D1: partial max over 7 j's (2 cols/thread) --------
__global__ void __launch_bounds__(256) maxredA() {
    int b = blockIdx.z, jc = blockIdx.y;
    int m4 = blockIdx.x * 256 + threadIdx.x;
    const float4* Wb = (const float4*)(g_W + (size_t)b * WSZ);
    float4 a0 = make_float4(0.f, 0.f, 0.f, 0.f), a1 = a0;
#pragma unroll
    for (int u = 0; u < 7; u++) {
        float4 v0 = Wb[(size_t)(jc * 7 + u) * 4096 + m4];
        float4 v1 = Wb[(size_t)(jc * 7 + u) * 4096 + m4 + 2048];
        a0.x = fmaxf(a0.x, v0.x); a0.y = fmaxf(a0.y, v0.y);
        a0.z = fmaxf(a0.z, v0.z); a0.w = fmaxf(a0.w, v0.w);
        a1.x = fmaxf(a1.x, v1.x); a1.y = fmaxf(a1.y, v1.y);
        a1.z = fmaxf(a1.z, v1.z); a1.w = fmaxf(a1.w, v1.w);
    }
    ((float4*)g_Q)[(b * 7 + jc) * 4096 + m4] = a0;
    ((float4*)g_Q)[(b * 7 + jc) * 4096 + m4 + 2048] = a1;
}

// ---------------- Kernel D2: combine + sqrt + norm partials ----------------
__global__ void __launch_bounds__(256) maxredB(float* __restrict__ out) {
    int b = blockIdx.y;
    int m4 = blockIdx.x * 256 + threadIdx.x;
    float4 a = make_float4(0.f, 0.f, 0.f, 0.f);
#pragma unroll
    for (int jc = 0; jc < 7; jc++) {
        float4 v = ((const float4*)g_Q)[(b * 7 + jc) * 4096 + m4];
        a.x = fmaxf(a.x, v.x); a.y = fmaxf(a.y, v.y);
        a.z = fmaxf(a.z, v.z); a.w = fmaxf(a.w, v.w);
    }
    float4 r = make_float4(sqrtf(a.x), sqrtf(a.y), sqrtf(a.z), sqrtf(a.w));
    ((float4*)(out + b * MM))[m4] = r;

    float v = r.x * r.x + r.y * r.y + r.z * r.z + r.w * r.w;
#pragma unroll
    for (int off = 16; off; off >>= 1) v += __shfl_down_sync(0xffffffffu, v, off);
    __shared__ float ssum[8];
    if ((threadIdx.x & 31) == 0) ssum[threadIdx.x >> 5] = v;
    __syncthreads();
    if (threadIdx.x == 0) {
        float s = 0.f;
#pragma unroll
        for (int i = 0; i < 8; i++) s += ssum[i];
        g_part[b * 64 + blockIdx.x] = s;
    }
}

__global__ void normk() {
    __shared__ float s[64];
    int b = blockIdx.x, t = threadIdx.x;
    s[t] = g_part[b * 64 + t];
    __syncthreads();
#pragma unroll
    for (int st = 32; st; st >>= 1) {
        if (t < st) s[t] += s[t + st];
        __syncthreads();
    }
    if (t == 0) g_norm[b] = s[0] + EPSV;
}

__global__ void __launch_bounds__(256) divk(float* __restrict__ out) {
    int i = blockIdx.x * 256 + threadIdx.x;
    out[i] = out[i] / g_norm[i >> 14];
}

// ---------------- launch ----------------------------------------------------
extern "C" void kernel_launch(void* const* d_in, const int* in_sizes, int n_in,
                              void* d_out, int out_size) {
    const float* x = (const float*)d_in[0];
    const float* w = (const float*)d_in[1];
    if (in_sizes[0] == NC * CIN) { const float* t = x; x = w; w = t; }
    float* out = (float*)d_out;

    pw4<<<dim3(4, 4, NB * 4), 256>>>(x, w);       // launch 1
    prep<<<dim3(NC, NB), 256>>>();                // launch 2
    zeroWk<<<6272, 256>>>();                      // launch 3 (zero W + part)

    int smem = 14848 + (2 * 32 * XDS + 16) * 2;   // 43,552 bytes
    cudaFuncSetAttribute(corr10, cudaFuncAttributeMaxDynamicSharedMemorySize, smem);
    corr10<<<dim3(25, 10, NB), 256, smem>>>();    // launch 4 -> ncu capture

    maxredA<<<dim3(8, 7, NB), 256>>>();
    maxredB<<<dim3(16, NB), 256>>>(out);
    normk<<<NB, 64>>>();
    divk<<<512, 256>>>(out);
}

// round 13
// speedup vs baseline: 1.3903x; 1.3903x over previous
#include <cuda_runtime.h>
#include <cuda_fp16.h>
#include <cstdint>

#define HW   196
#define NC   128
#define NB   8
#define CIN  512
#define NPIX 256
#define MM   16384
#define EPSV 1e-11f
#define KPAD 208            // K padded to 13 k-steps of 16
#define XDW  424            // global doubled-row width (halfs)
#define XRS  232            // Xr smem row stride (halfs)
#define XDS  224            // Xd smem row width (halfs)
#define WSZ  802816         // 4096*196 = 49*16384

// ---------------- device scratch (.bss zero-init) --------------------------
__device__ float  g_yp  [4][NB * NC * NPIX];
__device__ __half g_xrh [NB * NC * KPAD];
__device__ __half g_xdh [NB * NC * XDW];
__device__ __half g_xdh1[NB * NC * XDW];
__device__ float  g_W   [(size_t)NB * WSZ];   // [b][f], f=(a32*128+c)*196+p
__device__ float  g_Q   [NB * 7 * 16384];
__device__ float  g_part[NB * 64];
__device__ float  g_norm[NB];

// ---------------- Kernel A: partial y = W @ x (K-split by 4) ---------------
__global__ void __launch_bounds__(256) pw4(const float* __restrict__ x,
                                           const float* __restrict__ w) {
    __shared__ float xs[32][64];
    __shared__ float ws[32][32];
    int bz = blockIdx.z, b = bz >> 2, ks = bz & 3;
    int o0 = blockIdx.y * 32, px0 = blockIdx.x * 64;
    int tid = threadIdx.x, px = tid & 63, og = tid >> 6;
    float acc[8];
#pragma unroll
    for (int u = 0; u < 8; u++) acc[u] = 0.f;
    const float* xb = x + b * CIN * NPIX;
    int ibase = ks * 128;
    for (int i0 = ibase; i0 < ibase + 128; i0 += 32) {
        __syncthreads();
#pragma unroll
        for (int r = 0; r < 8; r++) {
            int idx = tid + r * 256;
            xs[idx >> 6][idx & 63] = xb[(i0 + (idx >> 6)) * NPIX + px0 + (idx & 63)];
        }
#pragma unroll
        for (int r = 0; r < 4; r++) {
            int idx = tid + r * 256;
            ws[idx >> 5][idx & 31] = w[(o0 + (idx >> 5)) * CIN + i0 + (idx & 31)];
        }
        __syncthreads();
#pragma unroll
        for (int i = 0; i < 32; i++) {
            float xv = xs[i][px];
#pragma unroll
            for (int u = 0; u < 8; u++)
                acc[u] = fmaf(ws[og * 8 + u][i], xv, acc[u]);
        }
    }
    float* yb = g_yp[ks] + b * NC * NPIX;
#pragma unroll
    for (int u = 0; u < 8; u++)
        yb[(o0 + og * 8 + u) * NPIX + px0 + px] = acc[u];
}

// ---------------- Kernel B: sum + relu + gaussian + fp16 prep ---------------
__global__ void __launch_bounds__(256) prep() {
    __shared__ float s[256];
    int b = blockIdx.y, c = blockIdx.x, t = threadIdx.x;
    int off = (b * NC + c) * NPIX + t;
    s[t] = fmaxf(g_yp[0][off] + g_yp[1][off] + g_yp[2][off] + g_yp[3][off], 0.f);
    __syncthreads();
    if (t < HW) {
        const float G0 = 0.63661977f, G1 = 0.08615711f, G2 = 0.01166010f;
        int oy = t / 14, ox = t - oy * 14;
        int r0 = oy * 16 + ox, r1 = r0 + 16, r2 = r0 + 32;
        float v = G2 * (s[r0] + s[r0 + 2] + s[r2] + s[r2 + 2])
                + G1 * (s[r0 + 1] + s[r1] + s[r1 + 2] + s[r2 + 1])
                + G0 * s[r1 + 1];
        __half h = __float2half_rn(v);
        g_xrh[(b * NC + c) * KPAD + (195 - t)] = h;
        __half* xd = g_xdh + (size_t)(b * NC + c) * XDW;
        xd[t]      = h;
        xd[t + HW] = h;
        if (t < 32) xd[t + 392] = h;
        __half* x1 = g_xdh1 + (size_t)(b * NC + c) * XDW;
        x1[t + 195] = h;
        if (t) x1[t - 1] = h;
        if (t < 33) x1[t + 391] = h;
    }
}

// ---------------- shim: zero g_part; keeps corr in ncu slot 4 --------------
__global__ void zerok() {
    int i = blockIdx.x * 256 + threadIdx.x;
    if (i < NB * 64) g_part[i] = 0.f;
}

__device__ __forceinline__ uint32_t smem_u32(const void* p) {
    uint32_t a;
    asm("{ .reg .u64 t; cvta.to.shared.u64 t, %1; cvt.u32.u64 %0, t; }"
        : "=r"(a) : "l"(p));
    return a;
}

// ---------------- Kernel C: fp16 mma corr, 512 thr, in-CTA 4-fold ----------
// CTA: M=128 (all a) x N=128 (16 c x 8 p), K=208. 16 warps = 4 wm x 4 wn.
// Warp tile 32m x 32n (Mt2 x Nt4): acc 32 regs, 2.0 wf/HMMA. occ target 2.
__global__ void __launch_bounds__(512, 2) corr11() {
    extern __shared__ char dyn[];
    __half* XrS = (__half*)dyn;                         // [128][XRS] 59392B
    __half* XdA = (__half*)(dyn + 128 * XRS * 2);       // [16][XDS]
    __half* XdB = XdA + 16 * XDS + 16;                  // [16][XDS], bank shift
    float*  sbuf = (float*)dyn;                         // epilogue overlay 48KB

    int b  = blockIdx.z;
    int c0 = blockIdx.y * 16;
    int p0 = blockIdx.x * 8;
    int tid = threadIdx.x;

    // stage Xr: 128 rows x 26 int4
    {
        const int4* xr = (const int4*)(g_xrh + (size_t)b * NC * KPAD);
        for (int i = tid; i < 3328; i += 512) {
            int r = i / 26, q = i - r * 26;
            *(int4*)(XrS + r * XRS + q * 8) = xr[r * 26 + q];
        }
    }
    // stage XdA (window, unshifted) and XdB (window, +1 shifted)
    for (int i = tid; i < 896; i += 512) {
        int sel = (i >= 448);
        int ii = sel ? (i - 448) : i;
        int r = ii / 28, q = ii - r * 28;
        const __half* src = (sel ? g_xdh1 : g_xdh)
                          + (size_t)(b * NC + c0 + r) * XDW + p0 + q * 8;
        __half* dst = (sel ? XdB : XdA) + r * XDS + q * 8;
        *(int4*)dst = *(const int4*)src;
    }
    __syncthreads();

    int lane = tid & 31, w = tid >> 5;
    int wm = w >> 2, wn = w & 3;
    int lr = lane >> 2, lk = lane & 3;

    // A addresses: warp wm covers a = wm*32 + mi*16 + (frag rows)
    uint32_t a_addr[2];
    {
        int arow = wm * 32 + (lane & 7) + ((lane >> 3) & 1) * 8;
        int acol = (lane >> 4) * 8;
        uint32_t base = smem_u32(XrS);
#pragma unroll
        for (int mi = 0; mi < 2; mi++)
            a_addr[mi] = base + (uint32_t)(((arow + mi * 16) * XRS + acol) * 2);
    }

    // B fragment: n (=lr) is p_local; parity-select copy for alignment
    const __half* brow[4];
    {
        const __half* pb = (lr & 1) ? (XdA + lr + 1) : (XdB + lr);
#pragma unroll
        for (int nt = 0; nt < 4; nt++)
            brow[nt] = pb + (wn * 4 + nt) * XDS + lk * 2;
    }

    float acc[2][4][4];
#pragma unroll
    for (int mi = 0; mi < 2; mi++)
#pragma unroll
        for (int nt = 0; nt < 4; nt++)
#pragma unroll
            for (int u = 0; u < 4; u++) acc[mi][nt][u] = 0.f;

#pragma unroll
    for (int k = 0; k < KPAD; k += 16) {
        uint32_t af[2][4];
#pragma unroll
        for (int mi = 0; mi < 2; mi++) {
            asm volatile(
                "ldmatrix.sync.aligned.m8n8.x4.shared.b16 {%0,%1,%2,%3}, [%4];"
                : "=r"(af[mi][0]), "=r"(af[mi][1]),
                  "=r"(af[mi][2]), "=r"(af[mi][3])
                : "r"(a_addr[mi] + (uint32_t)(k * 2)));
        }
#pragma unroll
        for (int nt = 0; nt < 4; nt++) {
            uint32_t b0 = *(const uint32_t*)(brow[nt] + k);
            uint32_t b1 = *(const uint32_t*)(brow[nt] + k + 8);
#pragma unroll
            for (int mi = 0; mi < 2; mi++) {
                asm volatile(
                    "mma.sync.aligned.m16n8k16.row.col.f32.f16.f16.f32 "
                    "{%0,%1,%2,%3},{%4,%5,%6,%7},{%8,%9},{%0,%1,%2,%3};"
                    : "+f"(acc[mi][nt][0]), "+f"(acc[mi][nt][1]),
                      "+f"(acc[mi][nt][2]), "+f"(acc[mi][nt][3])
                    : "r"(af[mi][0]), "r"(af[mi][1]),
                      "r"(af[mi][2]), "r"(af[mi][3]),
                      "r"(b0), "r"(b1));
            }
        }
    }

    // cross-warp fold over wm (a-group g = mi*16 + fragrow, same for all wm)
    __syncthreads();   // operands consumed; overlay sbuf
    if (wm != 0) {
        float* dst = sbuf + ((wm - 1) * 4 + wn) * 1024 + lane;
#pragma unroll
        for (int mi = 0; mi < 2; mi++)
#pragma unroll
            for (int nt = 0; nt < 4; nt++)
#pragma unroll
                for (int u = 0; u < 4; u++)
                    dst[((mi * 4 + nt) * 4 + u) * 32] = acc[mi][nt][u];
    }
    __syncthreads();
    if (wm == 0) {
        int pe = p0 + lk * 2;
        float* Wb = g_W + (size_t)b * WSZ;
        const float* s1 = sbuf + (0 * 4 + wn) * 1024 + lane;
        const float* s2 = sbuf + (1 * 4 + wn) * 1024 + lane;
        const float* s3 = sbuf + (2 * 4 + wn) * 1024 + lane;
#pragma unroll
        for (int mi = 0; mi < 2; mi++)
#pragma unroll
            for (int nt = 0; nt < 4; nt++) {
                float v[4];
#pragma unroll
                for (int u = 0; u < 4; u++) {
                    int sl = ((mi * 4 + nt) * 4 + u) * 32;
                    v[u] = fmaxf(fmaxf(acc[mi][nt][u], s1[sl]),
                                 fmaxf(s2[sl], s3[sl]));
                }
                if (pe < HW) {
                    int c  = c0 + wn * 4 + nt;
                    int s0 = (mi * 16 + lr) * 128 + c;
                    *(float2*)(Wb + (size_t)s0 * HW + pe) = make_float2(v[0], v[1]);
                    *(float2*)(Wb + (size_t)(s0 + 8 * 128) * HW + pe) =
                        make_float2(v[2], v[3]);
                }
            }
    }
}

// ---------------- Kernel D1: partial max over 7 j's (2 cols/thread) --------
__global__ void __launch_bounds__(256) maxredA() {
    int b = blockIdx.z, jc = blockIdx.y;
    int m4 = blockIdx.x * 256 + threadIdx.x;
    const float4* Wb = (const float4*)(g_W + (size_t)b * WSZ);
    float4 a0 = make_float4(0.f, 0.f, 0.f, 0.f), a1 = a0;
#pragma unroll
    for (int u = 0; u < 7; u++) {
        float4 v0 = Wb[(size_t)(jc * 7 + u) * 4096 + m4];
        float4 v1 = Wb[(size_t)(jc * 7 + u) * 4096 + m4 + 2048];
        a0.x = fmaxf(a0.x, v0.x); a0.y = fmaxf(a0.y, v0.y);
        a0.z = fmaxf(a0.z, v0.z); a0.w = fmaxf(a0.w, v0.w);
        a1.x = fmaxf(a1.x, v1.x); a1.y = fmaxf(a1.y, v1.y);
        a1.z = fmaxf(a1.z, v1.z); a1.w = fmaxf(a1.w, v1.w);
    }
    ((float4*)g_Q)[(b * 7 + jc) * 4096 + m4] = a0;
    ((float4*)g_Q)[(b * 7 + jc) * 4096 + m4 + 2048] = a1;
}

// ---------------- Kernel D2: combine + sqrt + norm partials ----------------
__global__ void __launch_bounds__(256) maxredB(float* __restrict__ out) {
    int b = blockIdx.y;
    int m4 = blockIdx.x * 256 + threadIdx.x;
    float4 a = make_float4(0.f, 0.f, 0.f, 0.f);
#pragma unroll
    for (int jc = 0; jc < 7; jc++) {
        float4 v = ((const float4*)g_Q)[(b * 7 + jc) * 4096 + m4];
        a.x = fmaxf(a.x, v.x); a.y = fmaxf(a.y, v.y);
        a.z = fmaxf(a.z, v.z); a.w = fmaxf(a.w, v.w);
    }
    float4 r = make_float4(sqrtf(a.x), sqrtf(a.y), sqrtf(a.z), sqrtf(a.w));
    ((float4*)(out + b * MM))[m4] = r;

    float v = r.x * r.x + r.y * r.y + r.z * r.z + r.w * r.w;
#pragma unroll
    for (int off = 16; off; off >>= 1) v += __shfl_down_sync(0xffffffffu, v, off);
    __shared__ float ssum[8];
    if ((threadIdx.x & 31) == 0) ssum[threadIdx.x >> 5] = v;
    __syncthreads();
    if (threadIdx.x == 0) {
        float s = 0.f;
#pragma unroll
        for (int i = 0; i < 8; i++) s += ssum[i];
        g_part[b * 64 + blockIdx.x] = s;
    }
}

__global__ void normk() {
    __shared__ float s[64];
    int b = blockIdx.x, t = threadIdx.x;
    s[t] = g_part[b * 64 + t];
    __syncthreads();
#pragma unroll
    for (int st = 32; st; st >>= 1) {
        if (t < st) s[t] += s[t + st];
        __syncthreads();
    }
    if (t == 0) g_norm[b] = s[0] + EPSV;
}

__global__ void __launch_bounds__(256) divk(float* __restrict__ out) {
    int i = blockIdx.x * 256 + threadIdx.x;
    out[i] = out[i] / g_norm[i >> 14];
}

// ---------------- launch ----------------------------------------------------
extern "C" void kernel_launch(void* const* d_in, const int* in_sizes, int n_in,
                              void* d_out, int out_size) {
    const float* x = (const float*)d_in[0];
    const float* w = (const float*)d_in[1];
    if (in_sizes[0] == NC * CIN) { const float* t = x; x = w; w = t; }
    float* out = (float*)d_out;

    pw4<<<dim3(4, 4, NB * 4), 256>>>(x, w);       // launch 1
    prep<<<dim3(NC, NB), 256>>>();                // launch 2
    zerok<<<2, 256>>>();                          // launch 3 (shim)

    int smem = (128 * XRS + 2 * 16 * XDS + 16) * 2;   // 73760 bytes
    cudaFuncSetAttribute(corr11, cudaFuncAttributeMaxDynamicSharedMemorySize, smem);
    corr11<<<dim3(25, 8, NB), 512, smem>>>();     // launch 4 -> ncu capture

    maxredA<<<dim3(8, 7, NB), 256>>>();
    maxredB<<<dim3(16, NB), 256>>>(out);
    normk<<<NB, 64>>>();
    divk<<<512, 256>>>(out);
}